// round 16
// baseline (speedup 1.0000x reference)
#include <cuda_runtime.h>
#include <cuda_fp16.h>
#include <cstdint>
#include <cstddef>

// Problem constants
#define NB 32
#define NT 512
#define NI 256
#define NH 512

// -------------------- device scratch (no allocations allowed) --------------------
// xp layout: [d][t][b(32)][row(2048)], row = unit*4 + gate  (gate: 0=i,1=f,2=g,3=o)
__device__ float    g_xp[2u * 512u * 32u * 2048u];   // 268 MB
// x pre-split fp16: [op(hi/lo)][t(512)][b(32)][i(256)]
__device__ __half   g_xh[2u * 512u * 32u * 256u];    // 16 MB
// h split-fp16 double buffer: [d][parity][op(hi/lo)][b(32)][k(512)] __half
__device__ __half   g_hs[2 * 2 * 2 * 32 * 512];
// per-producer step flags: flag[d][p] at stride 32 u32. 64 producers per dir.
__device__ unsigned g_flags[2 * 64 * 32];

// -------------------- helpers --------------------
__device__ __forceinline__ float tanh_fast(float x) {
    float r;
    asm("tanh.approx.f32 %0, %1;" : "=f"(r) : "f"(x));
    return r;
}
__device__ __forceinline__ float sigmoid_t(float x) {   // 0.5 + 0.5*tanh(x/2)
    return 0.5f + 0.5f * tanh_fast(0.5f * x);
}
__device__ __forceinline__ unsigned ld_acquire_gpu(const unsigned* p) {
    unsigned v;
    asm volatile("ld.acquire.gpu.u32 %0, [%1];" : "=r"(v) : "l"(p) : "memory");
    return v;
}
__device__ __forceinline__ void st_release_gpu(unsigned* p, unsigned v) {
    asm volatile("st.release.gpu.u32 [%0], %1;" :: "l"(p), "r"(v) : "memory");
}
__device__ __forceinline__ unsigned ld_acquire_sh(uint32_t addr) {
    unsigned v;
    asm volatile("ld.acquire.cta.shared.u32 %0, [%1];" : "=r"(v) : "r"(addr) : "memory");
    return v;
}
__device__ __forceinline__ void red_add_release_sh(uint32_t addr, unsigned v) {
    asm volatile("red.add.release.cta.shared.u32 [%0], %1;" :: "r"(addr), "r"(v) : "memory");
}
__device__ __forceinline__ uint32_t smem_to_u32(const void* smem_ptr) {
    uint32_t addr;
    asm("{ .reg .u64 tmp; cvta.to.shared.u64 tmp, %1; cvt.u32.u64 %0, tmp; }"
        : "=r"(addr) : "l"(smem_ptr));
    return addr;
}

// ldmatrix (sm_75+), mma.sync m16n8k16 f16->f32 (sm_80+), cp.async (sm_80+)
__device__ __forceinline__ void ldm_x4(uint32_t& r0, uint32_t& r1, uint32_t& r2, uint32_t& r3,
                                       uint32_t addr) {
    asm volatile("ldmatrix.sync.aligned.m8n8.x4.shared.b16 {%0,%1,%2,%3}, [%4];"
        : "=r"(r0), "=r"(r1), "=r"(r2), "=r"(r3) : "r"(addr));
}
__device__ __forceinline__ void mma16816(float* d, const uint32_t* a, const uint32_t* b) {
    asm volatile(
        "mma.sync.aligned.m16n8k16.row.col.f32.f16.f16.f32 "
        "{%0,%1,%2,%3}, {%4,%5,%6,%7}, {%8,%9}, {%0,%1,%2,%3};"
        : "+f"(d[0]), "+f"(d[1]), "+f"(d[2]), "+f"(d[3])
        : "r"(a[0]), "r"(a[1]), "r"(a[2]), "r"(a[3]), "r"(b[0]), "r"(b[1]));
}
#define CP_ASYNC16(smem_u32, gptr) \
    asm volatile("cp.async.cg.shared.global [%0], [%1], 16;" :: "r"(smem_u32), "l"(gptr))
#define CP_COMMIT()  asm volatile("cp.async.commit_group;" ::: "memory")
#define CP_WAIT0()   asm volatile("cp.async.wait_group 0;" ::: "memory")
#define CP_WAIT1()   asm volatile("cp.async.wait_group 1;" ::: "memory")
#define BAR_MMA()    asm volatile("bar.sync 1, 256;" ::: "memory")

// split a float into fp16 hi + fp16 lo
__device__ __forceinline__ void split16(float v, __half& hi, __half& lo) {
    hi = __float2half_rn(v);
    lo = __float2half_rn(v - __half2float(hi));
}

// ==================================================================================
// Phase A0: one-shot x split.  g_xh[op][t][b][i] = hi/lo fp16 of x[b][t][i].
// ==================================================================================
__global__ __launch_bounds__(256) void k_xsplit(const float* __restrict__ x) {
    int id = blockIdx.x * 256 + threadIdx.x;    // 0 .. 1048575
    int b   = id >> 15;
    int rem = id & 32767;
    int t   = rem >> 6;
    int i4  = rem & 63;
    float4 v = *(const float4*)(x + (size_t)id * 4);
    __half h0, l0, h1, l1, h2, l2, h3, l3;
    split16(v.x, h0, l0); split16(v.y, h1, l1);
    split16(v.z, h2, l2); split16(v.w, h3, l3);
    __half2 hh01 = __halves2half2(h0, h1), hh23 = __halves2half2(h2, h3);
    __half2 ll01 = __halves2half2(l0, l1), ll23 = __halves2half2(l2, l3);
    uint2 hv, lv;
    hv.x = *(uint32_t*)&hh01; hv.y = *(uint32_t*)&hh23;
    lv.x = *(uint32_t*)&ll01; lv.y = *(uint32_t*)&ll23;
    size_t dst = (((size_t)t * 32 + b) * 256) + i4 * 4;
    *(uint2*)(g_xh + dst)                     = hv;
    *(uint2*)(g_xh + 4194304u + dst)          = lv;   // op stride = 512*32*256
}

// ==================================================================================
// Phase A: HMMA input projections (3-pass split precision) with ping-pong x tiles:
// fetch(t+1) issued before compute(t); cp.async.wait_group 1 hides the fetch.
// ==================================================================================
#define XROWB  528
#define XA_HI  0
#define XA_LO  (XA_HI + 128 * XROWB)                 // 67584
#define XB0    (XA_LO + 128 * XROWB)                 // 135168 ; [hi 16896][lo 16896]
#define XB1    (XB0 + 2 * 32 * XROWB)                // 168960
#define XDST   (XB1 + 2 * 32 * XROWB)                // 202752 ; float[128*33] = 16896
#define XBIAS  (XDST + 16896)                        // 219648
#define XPROJ_SMEM (XBIAS + 640)                     // 220288

__global__ __launch_bounds__(256, 1) void k_xproj(
    const float* __restrict__ x,
    const float* __restrict__ Wf, const float* __restrict__ bf,
    const float* __restrict__ Wb, const float* __restrict__ bb)
{
    extern __shared__ char smem[];
    const uint32_t sb = smem_to_u32(smem);
    float* Dst   = (float*)(smem + XDST);
    float* biasS = (float*)(smem + XBIAS);

    const int d    = blockIdx.z;
    const int R0   = blockIdx.x * 128;
    const int t0   = blockIdx.y * 32;
    const int tid  = threadIdx.x;
    const int lane = tid & 31;
    const int wid  = tid >> 5;
    const float* W    = d ? Wb : Wf;
    const float* bias = d ? bb : bf;

    // ---- fused init: zero g_hs parity 0 (both dirs, hi+lo) + flags
    if (blockIdx.z == 0 && blockIdx.y == 0 && blockIdx.x < 8) {
        int t = blockIdx.x * 256 + tid;   // 0..2047
        #pragma unroll
        for (int r = 0; r < 4; r++) {
            int dd = r >> 1, op = r & 1;
            uint4* z = (uint4*)&g_hs[(((size_t)dd * 2 + 0) * 2 + op) * 32 * 512];
            z[t] = make_uint4(0, 0, 0, 0);
        }
        #pragma unroll
        for (int i = 0; i < 2; i++)
            g_flags[t + i * 2048] = 0u;
    }

    // ---- A stage: W rows hi/lo
    for (int idx = tid; idx < 8192; idx += 256) {
        int r  = idx >> 6;
        int i4 = idx & 63;
        int grow = R0 + r;
        int wrow = ((grow & 3) << 9) + (grow >> 2);
        float4 v = *(const float4*)(W + (size_t)wrow * 256 + i4 * 4);
        __half h0, l0, h1, l1, h2, l2, h3, l3;
        split16(v.x, h0, l0); split16(v.y, h1, l1);
        split16(v.z, h2, l2); split16(v.w, h3, l3);
        __half2 hh01 = __halves2half2(h0, h1), hh23 = __halves2half2(h2, h3);
        __half2 ll01 = __halves2half2(l0, l1), ll23 = __halves2half2(l2, l3);
        uint2 hv, lv;
        hv.x = *(uint32_t*)&hh01; hv.y = *(uint32_t*)&hh23;
        lv.x = *(uint32_t*)&ll01; lv.y = *(uint32_t*)&ll23;
        *(uint2*)(smem + XA_HI + r * XROWB + i4 * 8) = hv;
        *(uint2*)(smem + XA_LO + r * XROWB + i4 * 8) = lv;
    }
    if (tid < 128) {
        int grow = R0 + tid;
        biasS[tid] = bias[((grow & 3) << 9) + (grow >> 2)];
    }
    __syncthreads();

    const int mi = wid;
    const uint32_t a_off = (uint32_t)(mi * 16 + (lane & 15)) * XROWB + ((lane >> 4) & 1) * 16;
    const int b_row = (lane & 7) + ((lane & 16) >> 1);
    const uint32_t b_off = (uint32_t)b_row * XROWB + ((lane >> 3) & 1) * 16;

    const int b_w  = tid >> 3;
    const int rq_w = tid & 7;

    // staging lambda-equivalent constants (per thread 8 pieces per tile)
    // id over [op(2)][b(32)][c(32)] : op = id>>10, b = (id>>5)&31, c = id&31
    const int s_op = (tid + 0) >> 10;   // recomputed per j below; here placeholder

    // ---- prologue: fetch tile 0 into buffer 0
    {
        #pragma unroll
        for (int j = 0; j < 8; j++) {
            int id  = tid + j * 256;
            int op  = id >> 10;
            int rem = id & 1023;
            int b   = rem >> 5;
            int c   = rem & 31;
            const __half* src = g_xh + (size_t)op * 4194304u
                              + (((size_t)t0 * 32 + b) * 256) + c * 8;
            uint32_t dst = sb + XB0 + op * 16896 + b * XROWB + c * 16;
            CP_ASYNC16(dst, src);
        }
        CP_COMMIT();
    }

    for (int tl = 0; tl < 32; tl++) {
        const int t = t0 + tl;
        const uint32_t XB = (tl & 1) ? XB1 : XB0;

        // ---- issue fetch for tile tl+1 into the other buffer, then wait for tile tl
        if (tl + 1 < 32) {
            const int tn = t0 + tl + 1;
            const uint32_t XBN = ((tl + 1) & 1) ? XB1 : XB0;
            #pragma unroll
            for (int j = 0; j < 8; j++) {
                int id  = tid + j * 256;
                int op  = id >> 10;
                int rem = id & 1023;
                int b   = rem >> 5;
                int c   = rem & 31;
                const __half* src = g_xh + (size_t)op * 4194304u
                                  + (((size_t)tn * 32 + b) * 256) + c * 8;
                uint32_t dst = sb + XBN + op * 16896 + b * XROWB + c * 16;
                CP_ASYNC16(dst, src);
            }
            CP_COMMIT();
            CP_WAIT1();
        } else {
            CP_WAIT0();
        }
        __syncthreads();

        // ---- 3-pass MMA over K=256 (16 chunks)
        float accA[4][4], accB[4][4], accC[4][4];
        #pragma unroll
        for (int nt = 0; nt < 4; nt++)
            #pragma unroll
            for (int e = 0; e < 4; e++) { accA[nt][e] = 0.f; accB[nt][e] = 0.f; accC[nt][e] = 0.f; }

        {
            uint32_t aH = sb + XA_HI + a_off;
            uint32_t aL = sb + XA_LO + a_off;
            uint32_t bH0 = sb + XB + b_off;
            uint32_t bH1 = bH0 + 16 * XROWB;
            uint32_t bL0 = sb + XB + 16896 + b_off;
            uint32_t bL1 = bL0 + 16 * XROWB;
            #pragma unroll 2
            for (int kc = 0; kc < 16; kc++) {
                uint32_t ahi[4], alo[4], bh[8], bl[8];
                ldm_x4(ahi[0], ahi[1], ahi[2], ahi[3], aH + kc * 32);
                ldm_x4(alo[0], alo[1], alo[2], alo[3], aL + kc * 32);
                ldm_x4(bh[0], bh[1], bh[2], bh[3], bH0 + kc * 32);
                ldm_x4(bh[4], bh[5], bh[6], bh[7], bH1 + kc * 32);
                ldm_x4(bl[0], bl[1], bl[2], bl[3], bL0 + kc * 32);
                ldm_x4(bl[4], bl[5], bl[6], bl[7], bL1 + kc * 32);
                #pragma unroll
                for (int nt = 0; nt < 4; nt++) {
                    mma16816(accA[nt], ahi, bh + nt * 2);
                    mma16816(accB[nt], ahi, bl + nt * 2);
                    mma16816(accC[nt], alo, bh + nt * 2);
                }
            }
        }

        // ---- dump D tile to Dst
        {
            int rw  = mi * 16 + (lane >> 2);
            int cw0 = (lane & 3) * 2;
            #pragma unroll
            for (int nt = 0; nt < 4; nt++) {
                int col = nt * 8 + cw0;
                Dst[rw * 33 + col]           = accA[nt][0] + accB[nt][0] + accC[nt][0];
                Dst[rw * 33 + col + 1]       = accA[nt][1] + accB[nt][1] + accC[nt][1];
                Dst[(rw + 8) * 33 + col]     = accA[nt][2] + accB[nt][2] + accC[nt][2];
                Dst[(rw + 8) * 33 + col + 1] = accA[nt][3] + accB[nt][3] + accC[nt][3];
            }
        }
        __syncthreads();

        // ---- write out with bias (Dst reused only after next iter's mid sync)
        {
            float* op = g_xp + ((size_t)((d * 512 + t) * 32) + b_w) * 2048 + R0 + rq_w * 16;
            #pragma unroll
            for (int e = 0; e < 16; e += 4) {
                int r = rq_w * 16 + e;
                float4 o;
                o.x = Dst[(r + 0) * 33 + b_w] + biasS[r + 0];
                o.y = Dst[(r + 1) * 33 + b_w] + biasS[r + 1];
                o.z = Dst[(r + 2) * 33 + b_w] + biasS[r + 2];
                o.w = Dst[(r + 3) * 33 + b_w] + biasS[r + 3];
                *(float4*)(op + e) = o;
            }
        }
    }
}

// ==================================================================================
// Phase B: persistent recurrent kernel (v11: warp-specialized staging + double buf).
// 128 CTAs x 320 thr (8 MMA warps + 2 staging warps), ~172KB smem, 1 CTA/SM.
// CTA bid: d = bid>>6, p = bid&63 owns units j0 = p*8 (=32 gate rows, M=32).
// Staging thread st (0..63) owns producer st: polls flag st, cp.asyncs its 64
// pieces (2 op x 32 b at k16=st) into parity buffer BP(s&1), signals group st>>4.
// MMA warps: spin per-group ready counters (parity-indexed, accumulating), MMA,
// dump, named-bar(256), finalize, named-bar, release flag; then signal consumed.
// Counters: CNT[P][g] += 1 per staging thread (16/group/use, tgt 16*((s>>1)+1));
// CONS[P] += 1 per MMA warp per use (staging for s waits CONS[P] >= 8*(s>>1)).
// Staging warps never __syncthreads after init; MMA warps use bar.sync 1,256.
// ==================================================================================
#define ROWB   1040
#define BPAR   (2 * 32 * ROWB)               // 66560 per parity [hi 33280][lo 33280]
#define DST_O  (2 * BPAR)                    // 133120 ; float[32*33] = 4224
#define CNT_O  (DST_O + 4224)                // 137344 ; [P(2)][g(4)] stride 128
#define CONS_O (CNT_O + 1024)                // 138368 ; [P(2)] stride 128
#define AST_O  (CONS_O + 256)                // 138624 ; A staging (init only) 33280
#define RECUR_SMEM (AST_O + 33280)           // 171904

__global__ __launch_bounds__(320, 1) void k_recur(
    const float* __restrict__ Whf,
    const float* __restrict__ Whb,
    float* __restrict__ out)
{
    extern __shared__ char smem[];
    const uint32_t sb = smem_to_u32(smem);
    float* Dst = (float*)(smem + DST_O);

    const int bid  = blockIdx.x;
    const int d    = bid >> 6;
    const int p    = bid & 63;
    const int j0   = p * 8;
    const int tid  = threadIdx.x;
    const int lane = tid & 31;
    const int wid  = tid >> 5;
    const float* Wh = d ? Whb : Whf;

    // ---- init counters
    if (tid < 8)  *(unsigned*)(smem + CNT_O + tid * 128) = 0u;
    if (tid < 2)  *(unsigned*)(smem + CONS_O + tid * 128) = 0u;

    // ---- stage W-hi rows (ju*4+g) into AST (all 320 threads help)
    for (int idx = tid; idx < 32 * 512; idx += 320) {
        int row = idx >> 9;
        int k   = idx & 511;
        int ju  = row >> 2, g = row & 3;
        float wv = Wh[((size_t)(g * 512 + j0 + ju)) * 512 + k];
        *(__half*)(smem + AST_O + row * ROWB + k * 2) = __float2half_rn(wv);
    }
    __syncthreads();

    // ---- preload A fragments (MMA warps only)
    const int mi = (wid >> 2) & 1;       // 0..1 (valid for wid<8)
    const int ni = wid & 3;              // 0..3
    uint32_t a_frag[32][4];
    if (wid < 8) {
        const uint32_t a_off = (uint32_t)(mi * 16 + (lane & 15)) * ROWB + ((lane >> 4) & 1) * 16;
        uint32_t aH = sb + AST_O + a_off;
        #pragma unroll
        for (int kc = 0; kc < 32; kc++)
            ldm_x4(a_frag[kc][0], a_frag[kc][1], a_frag[kc][2], a_frag[kc][3], aH + kc * 32);
    }
    __syncthreads();

    unsigned* flags  = g_flags + d * 64 * 32;
    unsigned* myflag = g_flags + (size_t)bid * 32;
    __half*   hsd    = g_hs + (size_t)d * 2 * 2 * 32 * 512;   // [parity][op][b][k]

    if (wid >= 8) {
        // ============================ STAGING ROLE ============================
        const int st = tid - 256;            // 0..63 : producer + k16 piece
        unsigned* pf = flags + st * 32;
        const uint32_t cbase = sb + CNT_O + ((st >> 4) * 128);

        for (int s = 0; s < 512; s++) {
            const int P = s & 1;
            while (ld_acquire_gpu(pf) < (unsigned)s) { }
            if (s >= 2) {
                uint32_t ca = sb + CONS_O + P * 128;
                unsigned tgt = 8u * (unsigned)(s >> 1);
                while (ld_acquire_sh(ca) < tgt) { }
            }
            const uint4* hp = (const uint4*)(hsd + (size_t)P * 32768);
            const uint32_t dbase = sb + P * BPAR + st * 16;
            #pragma unroll 4
            for (int op = 0; op < 2; op++) {
                #pragma unroll
                for (int b = 0; b < 32; b++) {
                    CP_ASYNC16(dbase + op * 33280 + b * ROWB, hp + op * 2048 + b * 64 + st);
                }
            }
            CP_COMMIT();
            CP_WAIT0();
            red_add_release_sh(cbase + P * 512, 1u);   // CNT[P][g]: P*4*128 = P*512
        }
        return;
    }

    // ============================== MMA ROLE ==============================
    const uint32_t b_off = (uint32_t)(ni * 8 + (lane & 7)) * ROWB + ((lane >> 3) & 3) * 16;

    const int ju_f = tid & 7;
    const int b_f  = tid >> 3;
    const int jg_f = j0 + ju_f;
    float c_st = 0.0f;

    float4 xg;
    {
        const int tt0 = d ? 511 : 0;
        xg = *(const float4*)(g_xp + ((size_t)((d * 512 + tt0) * 32) + b_f) * 2048 + jg_f * 4);
    }

    for (int s = 0; s < 512; s++) {
        const int tt = d ? (511 - s) : s;
        const int P  = s & 1;
        const unsigned tgt = 16u * (unsigned)((s >> 1) + 1);

        // ---- (2) HMMA, pipelined per K-group against staging warps
        float accA[4] = {0.f, 0.f, 0.f, 0.f};   // Whi * hhi
        float accB[4] = {0.f, 0.f, 0.f, 0.f};   // Whi * hlo
        {
            uint32_t bH = sb + P * BPAR + b_off;
            uint32_t bL = bH + 33280;
            #pragma unroll
            for (int g = 0; g < 4; g++) {
                while (ld_acquire_sh(sb + CNT_O + P * 512 + g * 128) < tgt) { }
                #pragma unroll
                for (int kc = 8 * g; kc < 8 * g + 8; kc += 2) {
                    uint32_t bh[4], bl[4];
                    ldm_x4(bh[0], bh[1], bh[2], bh[3], bH + kc * 32);
                    ldm_x4(bl[0], bl[1], bl[2], bl[3], bL + kc * 32);
                    mma16816(accA, a_frag[kc],     bh);
                    mma16816(accA, a_frag[kc + 1], bh + 2);
                    mma16816(accB, a_frag[kc],     bl);
                    mma16816(accB, a_frag[kc + 1], bl + 2);
                }
            }
        }
        // signal: this warp is done reading parity-P B data
        if (lane == 0) red_add_release_sh(sb + CONS_O + P * 128, 1u);

        // ---- (3) dump D tile
        {
            int rw = mi * 16 + (lane >> 2);
            int cw = ni * 8 + (lane & 3) * 2;
            Dst[rw * 33 + cw]           = accA[0] + accB[0];
            Dst[rw * 33 + cw + 1]       = accA[1] + accB[1];
            Dst[(rw + 8) * 33 + cw]     = accA[2] + accB[2];
            Dst[(rw + 8) * 33 + cw + 1] = accA[3] + accB[3];
        }
        BAR_MMA();

        // ---- (4) finalize + publish (critical path kept minimal)
        float h;
        {
            const float* db = Dst + (4 * ju_f) * 33 + b_f;
            float gi = sigmoid_t(db[0]  + xg.x);
            float gf = sigmoid_t(db[33] + xg.y);
            float gg = tanh_fast(db[66] + xg.z);
            float go = sigmoid_t(db[99] + xg.w);
            c_st = gf * c_st + gi * gg;
            h = go * tanh_fast(c_st);

            __half hi = __float2half_rn(h);
            __half lo = __float2half_rn(h - __half2float(hi));
            __half* hw = hsd + (size_t)((s + 1) & 1) * 32768;
            hw[b_f * 512 + jg_f]         = hi;
            hw[16384 + b_f * 512 + jg_f] = lo;
        }
        BAR_MMA();
        if (tid == 0) st_release_gpu(myflag, (unsigned)(s + 1));

        // ---- (5) non-critical tail: DRAM out-write + next-step xp prefetch
        out[((size_t)b_f * 512 + tt) * 1024 + d * 512 + jg_f] = h;
        if (s + 1 < 512) {
            const int ttn = d ? (510 - s) : (s + 1);
            xg = *(const float4*)(g_xp + ((size_t)((d * 512 + ttn) * 32) + b_f) * 2048 + jg_f * 4);
        }
    }
}

// ==================================================================================
extern "C" void kernel_launch(void* const* d_in, const int* in_sizes, int n_in,
                              void* d_out, int out_size)
{
    const float* x    = (const float*)d_in[0];
    const float* Wihf = (const float*)d_in[1];
    const float* Whhf = (const float*)d_in[2];
    const float* bf   = (const float*)d_in[3];
    const float* Wihb = (const float*)d_in[4];
    const float* Whhb = (const float*)d_in[5];
    const float* bb   = (const float*)d_in[6];
    float* out = (float*)d_out;

    cudaFuncSetAttribute(k_xproj, cudaFuncAttributeMaxDynamicSharedMemorySize, XPROJ_SMEM);
    cudaFuncSetAttribute(k_recur, cudaFuncAttributeMaxDynamicSharedMemorySize, RECUR_SMEM);

    k_xsplit<<<4096, 256>>>(x);
    k_xproj<<<dim3(16, 16, 2), 256, XPROJ_SMEM>>>(x, Wihf, bf, Wihb, bb);
    k_recur<<<128, 320, RECUR_SMEM>>>(Whhf, Whhb, out);
}

// round 17
// speedup vs baseline: 1.3394x; 1.3394x over previous
#include <cuda_runtime.h>
#include <cuda_fp16.h>
#include <cstdint>
#include <cstddef>

// Problem constants
#define NB 32
#define NT 512
#define NI 256
#define NH 512

// -------------------- device scratch (no allocations allowed) --------------------
// xp layout: [d][t][b(32)][row(2048)], row = unit*4 + gate  (gate: 0=i,1=f,2=g,3=o)
__device__ float    g_xp[2u * 512u * 32u * 2048u];   // 268 MB
// x pre-split fp16: [op(hi/lo)][t(512)][b(32)][i(256)]
__device__ __half   g_xh[2u * 512u * 32u * 256u];    // 16 MB
// h split-fp16 double buffer: [d][parity][op(hi/lo)][b(32)][k(512)] __half
__device__ __half   g_hs[2 * 2 * 2 * 32 * 512];
// per-producer step flags: flag[d][p] at stride 32 u32. 64 producers per dir.
__device__ unsigned g_flags[2 * 64 * 32];

// -------------------- helpers --------------------
__device__ __forceinline__ float tanh_fast(float x) {
    float r;
    asm("tanh.approx.f32 %0, %1;" : "=f"(r) : "f"(x));
    return r;
}
__device__ __forceinline__ float sigmoid_t(float x) {   // 0.5 + 0.5*tanh(x/2)
    return 0.5f + 0.5f * tanh_fast(0.5f * x);
}
__device__ __forceinline__ unsigned ld_acquire_gpu(const unsigned* p) {
    unsigned v;
    asm volatile("ld.acquire.gpu.u32 %0, [%1];" : "=r"(v) : "l"(p) : "memory");
    return v;
}
__device__ __forceinline__ void st_release_gpu(unsigned* p, unsigned v) {
    asm volatile("st.release.gpu.u32 [%0], %1;" :: "l"(p), "r"(v) : "memory");
}
__device__ __forceinline__ unsigned ld_acquire_sh(uint32_t addr) {
    unsigned v;
    asm volatile("ld.acquire.cta.shared.u32 %0, [%1];" : "=r"(v) : "r"(addr) : "memory");
    return v;
}
__device__ __forceinline__ void red_add_release_sh(uint32_t addr, unsigned v) {
    asm volatile("red.add.release.cta.shared.u32 [%0], %1;" :: "r"(addr), "r"(v) : "memory");
}
__device__ __forceinline__ uint32_t smem_to_u32(const void* smem_ptr) {
    uint32_t addr;
    asm("{ .reg .u64 tmp; cvta.to.shared.u64 tmp, %1; cvt.u32.u64 %0, tmp; }"
        : "=r"(addr) : "l"(smem_ptr));
    return addr;
}

// ldmatrix (sm_75+), mma.sync m16n8k16 f16->f32 (sm_80+), cp.async (sm_80+)
__device__ __forceinline__ void ldm_x4(uint32_t& r0, uint32_t& r1, uint32_t& r2, uint32_t& r3,
                                       uint32_t addr) {
    asm volatile("ldmatrix.sync.aligned.m8n8.x4.shared.b16 {%0,%1,%2,%3}, [%4];"
        : "=r"(r0), "=r"(r1), "=r"(r2), "=r"(r3) : "r"(addr));
}
__device__ __forceinline__ void mma16816(float* d, const uint32_t* a, const uint32_t* b) {
    asm volatile(
        "mma.sync.aligned.m16n8k16.row.col.f32.f16.f16.f32 "
        "{%0,%1,%2,%3}, {%4,%5,%6,%7}, {%8,%9}, {%0,%1,%2,%3};"
        : "+f"(d[0]), "+f"(d[1]), "+f"(d[2]), "+f"(d[3])
        : "r"(a[0]), "r"(a[1]), "r"(a[2]), "r"(a[3]), "r"(b[0]), "r"(b[1]));
}
#define CP_ASYNC16(smem_u32, gptr) \
    asm volatile("cp.async.cg.shared.global [%0], [%1], 16;" :: "r"(smem_u32), "l"(gptr))
#define CP_COMMIT()  asm volatile("cp.async.commit_group;" ::: "memory")
#define CP_WAIT0()   asm volatile("cp.async.wait_group 0;" ::: "memory")
#define CP_WAIT1()   asm volatile("cp.async.wait_group 1;" ::: "memory")

// split a float into fp16 hi + fp16 lo
__device__ __forceinline__ void split16(float v, __half& hi, __half& lo) {
    hi = __float2half_rn(v);
    lo = __float2half_rn(v - __half2float(hi));
}

// ==================================================================================
// Phase A0: one-shot x split.  g_xh[op][t][b][i] = hi/lo fp16 of x[b][t][i].
// ==================================================================================
__global__ __launch_bounds__(256) void k_xsplit(const float* __restrict__ x) {
    int id = blockIdx.x * 256 + threadIdx.x;    // 0 .. 1048575
    int b   = id >> 15;
    int rem = id & 32767;
    int t   = rem >> 6;
    int i4  = rem & 63;
    float4 v = *(const float4*)(x + (size_t)id * 4);
    __half h0, l0, h1, l1, h2, l2, h3, l3;
    split16(v.x, h0, l0); split16(v.y, h1, l1);
    split16(v.z, h2, l2); split16(v.w, h3, l3);
    __half2 hh01 = __halves2half2(h0, h1), hh23 = __halves2half2(h2, h3);
    __half2 ll01 = __halves2half2(l0, l1), ll23 = __halves2half2(l2, l3);
    uint2 hv, lv;
    hv.x = *(uint32_t*)&hh01; hv.y = *(uint32_t*)&hh23;
    lv.x = *(uint32_t*)&ll01; lv.y = *(uint32_t*)&ll23;
    size_t dst = (((size_t)t * 32 + b) * 256) + i4 * 4;
    *(uint2*)(g_xh + dst)                     = hv;
    *(uint2*)(g_xh + 4194304u + dst)          = lv;   // op stride = 512*32*256
}

// ==================================================================================
// Phase A: HMMA input projections (3-pass split precision) with ping-pong x tiles:
// fetch(t+1) issued before compute(t); cp.async.wait_group 1 hides the fetch.
// ==================================================================================
#define XROWB  528
#define XA_HI  0
#define XA_LO  (XA_HI + 128 * XROWB)                 // 67584
#define XB0    (XA_LO + 128 * XROWB)                 // 135168 ; [hi 16896][lo 16896]
#define XB1    (XB0 + 2 * 32 * XROWB)                // 168960
#define XDST   (XB1 + 2 * 32 * XROWB)                // 202752 ; float[128*33] = 16896
#define XBIAS  (XDST + 16896)                        // 219648
#define XPROJ_SMEM (XBIAS + 640)                     // 220288

__global__ __launch_bounds__(256, 1) void k_xproj(
    const float* __restrict__ x,
    const float* __restrict__ Wf, const float* __restrict__ bf,
    const float* __restrict__ Wb, const float* __restrict__ bb)
{
    extern __shared__ char smem[];
    const uint32_t sb = smem_to_u32(smem);
    float* Dst   = (float*)(smem + XDST);
    float* biasS = (float*)(smem + XBIAS);

    const int d    = blockIdx.z;
    const int R0   = blockIdx.x * 128;
    const int t0   = blockIdx.y * 32;
    const int tid  = threadIdx.x;
    const int lane = tid & 31;
    const int wid  = tid >> 5;
    const float* W    = d ? Wb : Wf;
    const float* bias = d ? bb : bf;

    // ---- fused init: zero g_hs parity 0 (both dirs, hi+lo) + flags
    if (blockIdx.z == 0 && blockIdx.y == 0 && blockIdx.x < 8) {
        int t = blockIdx.x * 256 + tid;   // 0..2047
        #pragma unroll
        for (int r = 0; r < 4; r++) {
            int dd = r >> 1, op = r & 1;
            uint4* z = (uint4*)&g_hs[(((size_t)dd * 2 + 0) * 2 + op) * 32 * 512];
            z[t] = make_uint4(0, 0, 0, 0);
        }
        #pragma unroll
        for (int i = 0; i < 2; i++)
            g_flags[t + i * 2048] = 0u;
    }

    // ---- A stage: W rows hi/lo
    for (int idx = tid; idx < 8192; idx += 256) {
        int r  = idx >> 6;
        int i4 = idx & 63;
        int grow = R0 + r;
        int wrow = ((grow & 3) << 9) + (grow >> 2);
        float4 v = *(const float4*)(W + (size_t)wrow * 256 + i4 * 4);
        __half h0, l0, h1, l1, h2, l2, h3, l3;
        split16(v.x, h0, l0); split16(v.y, h1, l1);
        split16(v.z, h2, l2); split16(v.w, h3, l3);
        __half2 hh01 = __halves2half2(h0, h1), hh23 = __halves2half2(h2, h3);
        __half2 ll01 = __halves2half2(l0, l1), ll23 = __halves2half2(l2, l3);
        uint2 hv, lv;
        hv.x = *(uint32_t*)&hh01; hv.y = *(uint32_t*)&hh23;
        lv.x = *(uint32_t*)&ll01; lv.y = *(uint32_t*)&ll23;
        *(uint2*)(smem + XA_HI + r * XROWB + i4 * 8) = hv;
        *(uint2*)(smem + XA_LO + r * XROWB + i4 * 8) = lv;
    }
    if (tid < 128) {
        int grow = R0 + tid;
        biasS[tid] = bias[((grow & 3) << 9) + (grow >> 2)];
    }
    __syncthreads();

    const int mi = wid;
    const uint32_t a_off = (uint32_t)(mi * 16 + (lane & 15)) * XROWB + ((lane >> 4) & 1) * 16;
    const int b_row = (lane & 7) + ((lane & 16) >> 1);
    const uint32_t b_off = (uint32_t)b_row * XROWB + ((lane >> 3) & 1) * 16;

    const int b_w  = tid >> 3;
    const int rq_w = tid & 7;

    // ---- prologue: fetch tile 0 into buffer 0
    {
        #pragma unroll
        for (int j = 0; j < 8; j++) {
            int id  = tid + j * 256;
            int op  = id >> 10;
            int rem = id & 1023;
            int b   = rem >> 5;
            int c   = rem & 31;
            const __half* src = g_xh + (size_t)op * 4194304u
                              + (((size_t)t0 * 32 + b) * 256) + c * 8;
            uint32_t dst = sb + XB0 + op * 16896 + b * XROWB + c * 16;
            CP_ASYNC16(dst, src);
        }
        CP_COMMIT();
    }

    for (int tl = 0; tl < 32; tl++) {
        const int t = t0 + tl;
        const uint32_t XB = (tl & 1) ? XB1 : XB0;

        // ---- issue fetch for tile tl+1 into the other buffer, then wait for tile tl
        if (tl + 1 < 32) {
            const int tn = t0 + tl + 1;
            const uint32_t XBN = ((tl + 1) & 1) ? XB1 : XB0;
            #pragma unroll
            for (int j = 0; j < 8; j++) {
                int id  = tid + j * 256;
                int op  = id >> 10;
                int rem = id & 1023;
                int b   = rem >> 5;
                int c   = rem & 31;
                const __half* src = g_xh + (size_t)op * 4194304u
                                  + (((size_t)tn * 32 + b) * 256) + c * 8;
                uint32_t dst = sb + XBN + op * 16896 + b * XROWB + c * 16;
                CP_ASYNC16(dst, src);
            }
            CP_COMMIT();
            CP_WAIT1();
        } else {
            CP_WAIT0();
        }
        __syncthreads();

        // ---- 3-pass MMA over K=256 (16 chunks)
        float accA[4][4], accB[4][4], accC[4][4];
        #pragma unroll
        for (int nt = 0; nt < 4; nt++)
            #pragma unroll
            for (int e = 0; e < 4; e++) { accA[nt][e] = 0.f; accB[nt][e] = 0.f; accC[nt][e] = 0.f; }

        {
            uint32_t aH = sb + XA_HI + a_off;
            uint32_t aL = sb + XA_LO + a_off;
            uint32_t bH0 = sb + XB + b_off;
            uint32_t bH1 = bH0 + 16 * XROWB;
            uint32_t bL0 = sb + XB + 16896 + b_off;
            uint32_t bL1 = bL0 + 16 * XROWB;
            #pragma unroll 2
            for (int kc = 0; kc < 16; kc++) {
                uint32_t ahi[4], alo[4], bh[8], bl[8];
                ldm_x4(ahi[0], ahi[1], ahi[2], ahi[3], aH + kc * 32);
                ldm_x4(alo[0], alo[1], alo[2], alo[3], aL + kc * 32);
                ldm_x4(bh[0], bh[1], bh[2], bh[3], bH0 + kc * 32);
                ldm_x4(bh[4], bh[5], bh[6], bh[7], bH1 + kc * 32);
                ldm_x4(bl[0], bl[1], bl[2], bl[3], bL0 + kc * 32);
                ldm_x4(bl[4], bl[5], bl[6], bl[7], bL1 + kc * 32);
                #pragma unroll
                for (int nt = 0; nt < 4; nt++) {
                    mma16816(accA[nt], ahi, bh + nt * 2);
                    mma16816(accB[nt], ahi, bl + nt * 2);
                    mma16816(accC[nt], alo, bh + nt * 2);
                }
            }
        }

        // ---- dump D tile to Dst
        {
            int rw  = mi * 16 + (lane >> 2);
            int cw0 = (lane & 3) * 2;
            #pragma unroll
            for (int nt = 0; nt < 4; nt++) {
                int col = nt * 8 + cw0;
                Dst[rw * 33 + col]           = accA[nt][0] + accB[nt][0] + accC[nt][0];
                Dst[rw * 33 + col + 1]       = accA[nt][1] + accB[nt][1] + accC[nt][1];
                Dst[(rw + 8) * 33 + col]     = accA[nt][2] + accB[nt][2] + accC[nt][2];
                Dst[(rw + 8) * 33 + col + 1] = accA[nt][3] + accB[nt][3] + accC[nt][3];
            }
        }
        __syncthreads();

        // ---- write out with bias
        {
            float* op = g_xp + ((size_t)((d * 512 + t) * 32) + b_w) * 2048 + R0 + rq_w * 16;
            #pragma unroll
            for (int e = 0; e < 16; e += 4) {
                int r = rq_w * 16 + e;
                float4 o;
                o.x = Dst[(r + 0) * 33 + b_w] + biasS[r + 0];
                o.y = Dst[(r + 1) * 33 + b_w] + biasS[r + 1];
                o.z = Dst[(r + 2) * 33 + b_w] + biasS[r + 2];
                o.w = Dst[(r + 3) * 33 + b_w] + biasS[r + 3];
                *(float4*)(op + e) = o;
            }
        }
    }
}

// ==================================================================================
// Phase B: persistent recurrent kernel (v9.2, the proven 2340us config, verbatim).
// 128 CTAs x 256 thr, ~106KB smem, 1 CTA/SM, co-resident => spin-safe.
// A-in-registers, 2-pass split precision, x4-B ldmatrix, per-lane flag gating,
// pipelined staging via 4 K-group readiness counters, publish-first ordering.
// ==================================================================================
#define ROWB   1040
#define B_HI   0
#define B_LO   (B_HI + 32 * ROWB)
#define DST_O  (B_LO + 32 * ROWB)            // 66560 ; float[32*33] = 4224
#define CNT_O  (DST_O + 4224)                // 4 counters, stride 128B
#define AST_O  (CNT_O + 512)                 // A staging (init only) 33280
#define RECUR_SMEM (AST_O + 33280)

__global__ __launch_bounds__(256, 1) void k_recur(
    const float* __restrict__ Whf,
    const float* __restrict__ Whb,
    float* __restrict__ out)
{
    extern __shared__ char smem[];
    const uint32_t sb = smem_to_u32(smem);
    float* Dst = (float*)(smem + DST_O);

    const int bid  = blockIdx.x;
    const int d    = bid >> 6;
    const int p    = bid & 63;
    const int j0   = p * 8;
    const int tid  = threadIdx.x;
    const int lane = tid & 31;
    const int wid  = tid >> 5;
    const int mi   = wid >> 2;           // 0..1  m-tile
    const int ni   = wid & 3;            // 0..3  n-tile
    const float* Wh = d ? Whb : Whf;

    // ---- zero group counters
    if (tid < 4) *(unsigned*)(smem + CNT_O + tid * 128) = 0u;

    // ---- stage W-hi rows (ju*4+g) into AST, then preload A fragments to registers
    for (int idx = tid; idx < 32 * 512; idx += 256) {
        int row = idx >> 9;
        int k   = idx & 511;
        int ju  = row >> 2, g = row & 3;
        float wv = Wh[((size_t)(g * 512 + j0 + ju)) * 512 + k];
        *(__half*)(smem + AST_O + row * ROWB + k * 2) = __float2half_rn(wv);
    }
    __syncthreads();

    uint32_t a_frag[32][4];
    {
        const uint32_t a_off = (uint32_t)(mi * 16 + (lane & 15)) * ROWB + ((lane >> 4) & 1) * 16;
        uint32_t aH = sb + AST_O + a_off;
        #pragma unroll
        for (int kc = 0; kc < 32; kc++)
            ldm_x4(a_frag[kc][0], a_frag[kc][1], a_frag[kc][2], a_frag[kc][3], aH + kc * 32);
    }
    __syncthreads();

    unsigned* flags  = g_flags + d * 64 * 32;
    unsigned* myflag = g_flags + (size_t)bid * 32;
    __half*   hsd    = g_hs + (size_t)d * 2 * 2 * 32 * 512;   // [parity][op][b][k]

    // B x4 lane offset: rows ni*8 + (lane&7); 16B col group (lane>>3)&3 spans 2 chunks
    const uint32_t b_off = (uint32_t)(ni * 8 + (lane & 7)) * ROWB + ((lane >> 3) & 3) * 16;

    const int ju_f = tid & 7;
    const int b_f  = tid >> 3;
    const int jg_f = j0 + ju_f;
    const int myprod = tid & 63;               // piece/producer this thread stages
    const uint32_t mycnt = sb + CNT_O + (myprod >> 4) * 128;
    float c_st = 0.0f;

    float4 xg;
    {
        const int tt0 = d ? 511 : 0;
        xg = *(const float4*)(g_xp + ((size_t)((d * 512 + tt0) * 32) + b_f) * 2048 + jg_f * 4);
    }

    for (int s = 0; s < 512; s++) {
        const int tt = d ? (511 - s) : s;

        // ---- (1) stage: poll my producer, cp.async my 16 pieces, signal my group
        while (ld_acquire_gpu(flags + myprod * 32) < (unsigned)s) { }
        {
            const uint4* hp = (const uint4*)(hsd + (size_t)(s & 1) * 2 * 32 * 512);
            #pragma unroll
            for (int i = 0; i < 16; i++) {
                int id  = tid + i * 256;
                int op  = id >> 11;
                int b   = (id >> 6) & 31;
                int k16 = id & 63;
                uint32_t daddr = sb + (op ? B_LO : B_HI) + b * ROWB + k16 * 16;
                CP_ASYNC16(daddr, hp + id);
            }
            CP_COMMIT();
            CP_WAIT0();
            red_add_release_sh(mycnt, 1u);
        }

        // ---- (2) HMMA, pipelined per K-group: spin group counter, then 4 iters
        float accA[4] = {0.f, 0.f, 0.f, 0.f};   // Whi * hhi
        float accB[4] = {0.f, 0.f, 0.f, 0.f};   // Whi * hlo
        {
            uint32_t bH = sb + B_HI + b_off;
            uint32_t bL = sb + B_LO + b_off;
            const unsigned tgt = 64u * (unsigned)(s + 1);
            #pragma unroll
            for (int g = 0; g < 4; g++) {
                while (ld_acquire_sh(sb + CNT_O + g * 128) < tgt) { }
                #pragma unroll
                for (int kc = 8 * g; kc < 8 * g + 8; kc += 2) {
                    uint32_t bh[4], bl[4];
                    ldm_x4(bh[0], bh[1], bh[2], bh[3], bH + kc * 32);
                    ldm_x4(bl[0], bl[1], bl[2], bl[3], bL + kc * 32);
                    mma16816(accA, a_frag[kc],     bh);
                    mma16816(accA, a_frag[kc + 1], bh + 2);
                    mma16816(accB, a_frag[kc],     bl);
                    mma16816(accB, a_frag[kc + 1], bl + 2);
                }
            }
        }

        // ---- (3) dump D tile
        {
            int rw = mi * 16 + (lane >> 2);
            int cw = ni * 8 + (lane & 3) * 2;
            Dst[rw * 33 + cw]           = accA[0] + accB[0];
            Dst[rw * 33 + cw + 1]       = accA[1] + accB[1];
            Dst[(rw + 8) * 33 + cw]     = accA[2] + accB[2];
            Dst[(rw + 8) * 33 + cw + 1] = accA[3] + accB[3];
        }
        __syncthreads();

        // ---- (4) finalize + publish (critical path kept minimal)
        float h;
        {
            const float* db = Dst + (4 * ju_f) * 33 + b_f;
            float gi = sigmoid_t(db[0]  + xg.x);
            float gf = sigmoid_t(db[33] + xg.y);
            float gg = tanh_fast(db[66] + xg.z);
            float go = sigmoid_t(db[99] + xg.w);
            c_st = gf * c_st + gi * gg;
            h = go * tanh_fast(c_st);

            __half hi = __float2half_rn(h);
            __half lo = __float2half_rn(h - __half2float(hi));
            __half* hw = hsd + (size_t)((s + 1) & 1) * 2 * 32 * 512;
            hw[b_f * 512 + jg_f]         = hi;
            hw[16384 + b_f * 512 + jg_f] = lo;
        }
        __syncthreads();
        if (tid == 0) st_release_gpu(myflag, (unsigned)(s + 1));

        // ---- (5) non-critical tail: DRAM out-write + next-step xp prefetch
        out[((size_t)b_f * 512 + tt) * 1024 + d * 512 + jg_f] = h;
        if (s + 1 < 512) {
            const int ttn = d ? (510 - s) : (s + 1);
            xg = *(const float4*)(g_xp + ((size_t)((d * 512 + ttn) * 32) + b_f) * 2048 + jg_f * 4);
        }
    }
}

// ==================================================================================
extern "C" void kernel_launch(void* const* d_in, const int* in_sizes, int n_in,
                              void* d_out, int out_size)
{
    const float* x    = (const float*)d_in[0];
    const float* Wihf = (const float*)d_in[1];
    const float* Whhf = (const float*)d_in[2];
    const float* bf   = (const float*)d_in[3];
    const float* Wihb = (const float*)d_in[4];
    const float* Whhb = (const float*)d_in[5];
    const float* bb   = (const float*)d_in[6];
    float* out = (float*)d_out;

    cudaFuncSetAttribute(k_xproj, cudaFuncAttributeMaxDynamicSharedMemorySize, XPROJ_SMEM);
    cudaFuncSetAttribute(k_recur, cudaFuncAttributeMaxDynamicSharedMemorySize, RECUR_SMEM);

    k_xsplit<<<4096, 256>>>(x);
    k_xproj<<<dim3(16, 16, 2), 256, XPROJ_SMEM>>>(x, Wihf, bf, Wihb, bb);
    k_recur<<<128, 256, RECUR_SMEM>>>(Whhf, Whhb, out);
}